// round 5
// baseline (speedup 1.0000x reference)
#include <cuda_runtime.h>

// XAJ hydrological scan: T=730, B=16384, evap MLP 8->16->8->1.
// Round 5 = Round 4 with the __exp2f build bug fixed (PTX ex2/lg2 wrappers).
// Design: R1 shape (1 basin/thread, 512 warps = 1/SMSP on 128 SMs), f32x2
// packing only where register-neutral (layers 1+2), no persistent software
// pipeline (R3's 255-reg spill), MUFU log2 issued off-chain, fdividef sigmoid.
#define T_STEPS 730
#define NBASIN  16384
#define NH1     16
#define NH2     8
#define EPSV    1e-5f

// Packed 2xFP32 FMA (sm_100+; PTX-only). Bit-identical to two fmaf's.
__device__ __forceinline__ float2 ffma2(float2 a, float2 b, float2 c) {
    float2 d;
    asm("fma.rn.f32x2 %0, %1, %2, %3;"
        : "=l"(reinterpret_cast<unsigned long long&>(d))
        : "l"(reinterpret_cast<unsigned long long&>(a)),
          "l"(reinterpret_cast<unsigned long long&>(b)),
          "l"(reinterpret_cast<unsigned long long&>(c)));
    return d;
}
// Duplicate a scalar into both lanes (1 MOV).
__device__ __forceinline__ float2 dup2(float s) {
    float2 d;
    asm("mov.b64 %0, {%1, %1};"
        : "=l"(reinterpret_cast<unsigned long long&>(d)) : "f"(s));
    return d;
}
// MUFU.EX2 / MUFU.LG2 — the same HW ops __expf/__powf decompose into.
__device__ __forceinline__ float ex2f(float x) {
    float r; asm("ex2.approx.f32 %0, %1;" : "=f"(r) : "f"(x)); return r;
}
__device__ __forceinline__ float lg2f(float x) {
    float r; asm("lg2.approx.f32 %0, %1;" : "=f"(r) : "f"(x)); return r;
}

__global__ __launch_bounds__(128, 1)
void xaj_dpl5_kernel(const float2* __restrict__ p_and_e,
                     const float*  __restrict__ kc_,
                     const float*  __restrict__ um_,
                     const float*  __restrict__ lm_,
                     const float*  __restrict__ dm_,
                     const float*  __restrict__ b_,
                     const float*  __restrict__ im_,
                     const float*  __restrict__ c_,
                     const float*  __restrict__ w0_,
                     const float*  __restrict__ W1,
                     const float*  __restrict__ b1,
                     const float*  __restrict__ W2,
                     const float*  __restrict__ b2,
                     const float*  __restrict__ W3,
                     const float*  __restrict__ b3,
                     float4*       __restrict__ out)
{
    // W2 [16,8] broadcast from shared via LDS.128.
    __shared__ float sW2[NH1 * NH2];
    if (threadIdx.x < NH1 * NH2) sW2[threadIdx.x] = W2[threadIdx.x];
    __syncthreads();

    const int bas = blockIdx.x * blockDim.x + threadIdx.x;

    // Per-basin constants
    const float kc = kc_[bas];
    const float um = um_[bas];
    const float lm = lm_[bas];
    const float dm = dm_[bas];
    const float bb = b_[bas];
    const float im = im_[bas];
    const float cc = c_[bas];
    float w = w0_[bas];

    const float wm      = um + lm + dm;
    const float one_b   = 1.0f + bb;
    const float wmm     = wm * one_b;
    const float inv_b1  = 1.0f / one_b;
    const float inv_wm  = 1.0f / wm;
    const float inv_wmm = 1.0f / wmm;
    const float wm_eps  = wm - EPSV;

    // Layer-1 weights as hidden-unit pairs; constant features folded into h1bp.
    float2 w5p[8], w6p[8], w7p[8], h1bp[8];
#pragma unroll
    for (int p = 0; p < 8; p++) {
        const int i0 = 2 * p, i1 = 2 * p + 1;
        w5p[p] = make_float2(W1[5 * NH1 + i0], W1[5 * NH1 + i1]);
        w6p[p] = make_float2(W1[6 * NH1 + i0], W1[6 * NH1 + i1]);
        w7p[p] = make_float2(W1[7 * NH1 + i0], W1[7 * NH1 + i1]);
        float hb0 = b1[i0] + kc * W1[i0] + um * W1[NH1 + i0] + lm * W1[2 * NH1 + i0]
                  + dm * W1[3 * NH1 + i0] + cc * W1[4 * NH1 + i0];
        float hb1 = b1[i1] + kc * W1[i1] + um * W1[NH1 + i1] + lm * W1[2 * NH1 + i1]
                  + dm * W1[3 * NH1 + i1] + cc * W1[4 * NH1 + i1];
        h1bp[p] = make_float2(hb0, hb1);
    }
    float2 rb2p[4];
#pragma unroll
    for (int k = 0; k < 4; k++) rb2p[k] = make_float2(b2[2 * k], b2[2 * k + 1]);
    float rw3[NH2];
#pragma unroll
    for (int k = 0; k < NH2; k++) rw3[k] = W3[k];
    const float rb3 = b3[0];

    // Forcing: distance-2 prefetch (hides ~577-cyc DRAM latency).
    const float2* pe_ptr = p_and_e + bas;
    float2 pe_a = pe_ptr[0];
    float2 pe_b = pe_ptr[NBASIN];

    float4* out_ptr = out + bas;

#pragma unroll 2
    for (int t = 0; t < T_STEPS; t++) {
        const float2 pe = pe_a;
        pe_a = pe_b;
        if (t + 2 < T_STEPS) pe_b = pe_ptr[(size_t)(t + 2) * NBASIN];

        const float prcp = fmaxf(pe.x, 0.0f);
        const float pet  = fmaxf(pe.y, 0.0f);
        const float kpet = kc * pet;
        const float w0c  = fminf(fmaxf(w, 0.0f), wm_eps);

        // Off-chain early: log2 half of powf(frac, inv_b1) starts right after w0c.
        const float frac  = fminf(fmaxf(fmaf(-w0c, inv_wm, 1.0f), EPSV), 1.0f);
        const float l2f   = lg2f(frac);                    // MUFU.LG2, off critical path
        const float a_xaj = wmm * (1.0f - ex2f(inv_b1 * l2f));
        const float r_base = w0c - wm;                     // r_full = pe_net + r_base

        // ---- layer 1: forcing partial (off-chain) + w0c term, packed pairs ----
        float2 h[8];
        {
            const float2 prd = dup2(prcp), ped = dup2(pet), w0d = dup2(w0c);
#pragma unroll
            for (int p = 0; p < 8; p++) {
                float2 hh = ffma2(ped, w7p[p], ffma2(prd, w6p[p], h1bp[p]));
                hh = ffma2(w0d, w5p[p], hh);
                h[p] = make_float2(fmaxf(hh.x, 0.0f), fmaxf(hh.y, 0.0f));
            }
        }

        // ---- layer 2: 16x8 matvec, accumulators packed (k,k+1) ----
        float2 a01 = rb2p[0], a23 = rb2p[1], a45 = rb2p[2], a67 = rb2p[3];
#pragma unroll
        for (int j = 0; j < NH1; j++) {
            const float4 wA = *reinterpret_cast<const float4*>(&sW2[j * NH2]);
            const float4 wB = *reinterpret_cast<const float4*>(&sW2[j * NH2 + 4]);
            const float hj = (j & 1) ? h[j >> 1].y : h[j >> 1].x;
            const float2 hd = dup2(hj);
            a01 = ffma2(hd, *reinterpret_cast<const float2*>(&wA.x), a01);
            a23 = ffma2(hd, *reinterpret_cast<const float2*>(&wA.z), a23);
            a45 = ffma2(hd, *reinterpret_cast<const float2*>(&wB.x), a45);
            a67 = ffma2(hd, *reinterpret_cast<const float2*>(&wB.z), a67);
        }

        // ---- layer 3 (scalar tree) ----
        float y0 = rb3 + fmaxf(a01.x, 0.0f) * rw3[0];
        float y1 = fmaxf(a01.y, 0.0f) * rw3[1];
        float y2 = fmaxf(a23.x, 0.0f) * rw3[2];
        float y3 = fmaxf(a23.y, 0.0f) * rw3[3];
        y0 += fmaxf(a45.x, 0.0f) * rw3[4];
        y1 += fmaxf(a45.y, 0.0f) * rw3[5];
        y2 += fmaxf(a67.x, 0.0f) * rw3[6];
        y3 += fmaxf(a67.y, 0.0f) * rw3[7];
        const float y = (y0 + y1) + (y2 + y3);

        // sigmoid * kc * pet:  e = kpet / (1 + exp(-y)) (MUFU EX2 + MUFU RCP)
        const float ex = ex2f(-1.442695040888963f * y);
        const float e  = __fdividef(kpet, 1.0f + ex);

        // ---- XAJ water balance ----
        const float pd     = prcp - e;
        const float pe_net = fmaxf(pd, 0.0f);
        const float resid  = fminf(fmaxf(fmaf(-(pe_net + a_xaj), inv_wmm, 1.0f), 0.0f), 1.0f);
        // resid==0 exactly when pe_net + a >= wmm; ex2(one_b*lg2(0)) = ex2(-inf) = 0,
        // so this is branchlessly identical to the reference's where().
        const float rp  = ex2f(one_b * lg2f(resid));
        const float r   = fmaxf(pe_net + r_base + wm * rp, 0.0f);
        const float rim = pe_net * im;

        w = fminf(fmaxf(w0c + pd - r, 0.0f), wm_eps);

        out_ptr[0] = make_float4(r, rim, e, pe_net);
        out_ptr += NBASIN;
    }
}

extern "C" void kernel_launch(void* const* d_in, const int* in_sizes, int n_in,
                              void* d_out, int out_size)
{
    (void)in_sizes; (void)n_in; (void)out_size;
    const float2* p_and_e = (const float2*)d_in[0];
    const float*  kc = (const float*)d_in[1];
    const float*  um = (const float*)d_in[2];
    const float*  lm = (const float*)d_in[3];
    const float*  dm = (const float*)d_in[4];
    const float*  b  = (const float*)d_in[5];
    const float*  im = (const float*)d_in[6];
    const float*  c  = (const float*)d_in[7];
    const float*  w0 = (const float*)d_in[8];
    const float*  W1 = (const float*)d_in[9];
    const float*  b1 = (const float*)d_in[10];
    const float*  W2 = (const float*)d_in[11];
    const float*  b2 = (const float*)d_in[12];
    const float*  W3 = (const float*)d_in[13];
    const float*  b3 = (const float*)d_in[14];
    float4* out = (float4*)d_out;

    // 16384 threads = 512 warps, 1 per SMSP on 128 SMs (max fill for B=16384).
    xaj_dpl5_kernel<<<128, 128>>>(p_and_e, kc, um, lm, dm, b, im, c, w0,
                                  W1, b1, W2, b2, W3, b3, out);
}

// round 6
// speedup vs baseline: 1.1814x; 1.1814x over previous
#include <cuda_runtime.h>

// XAJ hydrological scan: T=730, B=16384, evap MLP 8->16->8->1.
// Round 6: cooperative THREAD PAIRS — each basin is computed by 2 threads
// (even lane: hidden units 0-7, odd lane: 8-15). 32768 threads = 1024 warps
// = ~2 warps/SMSP so co-resident warps hide each other's latency stalls
// (R1's solo-warp issue efficiency was only 32%). f32x2 abandoned: its
// register-pair alignment constraints pushed ptxas to 254 regs 3 rounds
// in a row and killed the schedule.
#define T_STEPS 730
#define NBASIN  16384
#define NH1     16
#define NH2     8
#define EPSV    1e-5f

// MUFU.EX2 / MUFU.LG2 — the ops __expf/__powf decompose into.
__device__ __forceinline__ float ex2f(float x) {
    float r; asm("ex2.approx.f32 %0, %1;" : "=f"(r) : "f"(x)); return r;
}
__device__ __forceinline__ float lg2f(float x) {
    float r; asm("lg2.approx.f32 %0, %1;" : "=f"(r) : "f"(x)); return r;
}

__global__ __launch_bounds__(64)
void xaj_pair_kernel(const float2* __restrict__ p_and_e,
                     const float*  __restrict__ kc_,
                     const float*  __restrict__ um_,
                     const float*  __restrict__ lm_,
                     const float*  __restrict__ dm_,
                     const float*  __restrict__ b_,
                     const float*  __restrict__ im_,
                     const float*  __restrict__ c_,
                     const float*  __restrict__ w0_,
                     const float*  __restrict__ W1,
                     const float*  __restrict__ b1,
                     const float*  __restrict__ W2,
                     const float*  __restrict__ b2,
                     const float*  __restrict__ W3,
                     const float*  __restrict__ b3,
                     float2*       __restrict__ out2)
{
    // W2 [16,8] broadcast from shared via LDS.128.
    __shared__ float sW2[NH1 * NH2];
    for (int i = threadIdx.x; i < NH1 * NH2; i += 64) sW2[i] = W2[i];
    __syncthreads();

    const int gt    = blockIdx.x * 64 + threadIdx.x;  // 0..32767
    const int bas   = gt >> 1;                        // basin id
    const int half  = gt & 1;                         // 0: units 0-7, 1: units 8-15
    const int jbase = half * 8;

    // Per-basin constants (held by BOTH lanes of the pair)
    const float kc = kc_[bas];
    const float um = um_[bas];
    const float lm = lm_[bas];
    const float dm = dm_[bas];
    const float bb = b_[bas];
    const float im = im_[bas];
    const float cc = c_[bas];
    float w = w0_[bas];

    const float wm      = um + lm + dm;
    const float one_b   = 1.0f + bb;
    const float wmm     = wm * one_b;
    const float inv_b1  = 1.0f / one_b;
    const float inv_wm  = 1.0f / wm;
    const float inv_wmm = 1.0f / wmm;
    const float wm_eps  = wm - EPSV;

    // This lane's half of layer 1: hidden units [jbase, jbase+8).
    // Constant features (kc,um,lm,dm,c) folded into h1b.
    float w5[8], w6[8], w7[8], h1b[8];
#pragma unroll
    for (int p = 0; p < 8; p++) {
        const int i = jbase + p;
        w5[p] = W1[5 * NH1 + i];
        w6[p] = W1[6 * NH1 + i];
        w7[p] = W1[7 * NH1 + i];
        h1b[p] = b1[i] + kc * W1[i] + um * W1[NH1 + i] + lm * W1[2 * NH1 + i]
               + dm * W1[3 * NH1 + i] + cc * W1[4 * NH1 + i];
    }
    // Even lane seeds accumulators with b2; odd lane with 0 (avoids double add).
    float acc_init[NH2];
#pragma unroll
    for (int k = 0; k < NH2; k++) acc_init[k] = half ? 0.0f : b2[k];
    float rw3[NH2];
#pragma unroll
    for (int k = 0; k < NH2; k++) rw3[k] = W3[k];
    const float rb3 = b3[0];

    // Forcing: both lanes read the same float2 (L1 broadcast); distance-2 prefetch.
    const float2* pe_ptr = p_and_e + bas;
    float2 pe_a = pe_ptr[0];
    float2 pe_b = pe_ptr[NBASIN];

    // Output: float4 per (t, basin); even lane writes .xy=(r,rim), odd .zw=(e,pe_net).
    float2* out_ptr = out2 + (size_t)2 * bas + half;

#pragma unroll 2
    for (int t = 0; t < T_STEPS; t++) {
        const float2 pe = pe_a;
        pe_a = pe_b;
        if (t + 2 < T_STEPS) pe_b = pe_ptr[(size_t)(t + 2) * NBASIN];

        const float prcp = fmaxf(pe.x, 0.0f);
        const float pet  = fmaxf(pe.y, 0.0f);
        const float kpet = kc * pet;
        const float w0c  = fminf(fmaxf(w, 0.0f), wm_eps);

        // Off-chain early: lg2 half of powf(frac, inv_b1).
        const float frac  = fminf(fmaxf(fmaf(-w0c, inv_wm, 1.0f), EPSV), 1.0f);
        const float a_xaj = wmm * (1.0f - ex2f(inv_b1 * lg2f(frac)));
        const float r_base = w0c - wm;               // r_full = pe_net + r_base

        // ---- layer 1: this lane's 8 hidden units ----
        float h[8];
#pragma unroll
        for (int p = 0; p < 8; p++) {
            float hh = h1b[p] + w0c * w5[p] + prcp * w6[p] + pet * w7[p];
            h[p] = fmaxf(hh, 0.0f);
        }

        // ---- layer 2: partial 8x8 matvec over this lane's hidden units ----
        float a0 = acc_init[0], a1 = acc_init[1], a2 = acc_init[2], a3 = acc_init[3];
        float a4 = acc_init[4], a5 = acc_init[5], a6 = acc_init[6], a7 = acc_init[7];
#pragma unroll
        for (int p = 0; p < 8; p++) {
            const float4 wA = *reinterpret_cast<const float4*>(&sW2[(jbase + p) * NH2]);
            const float4 wB = *reinterpret_cast<const float4*>(&sW2[(jbase + p) * NH2 + 4]);
            const float hp = h[p];
            a0 += hp * wA.x; a1 += hp * wA.y; a2 += hp * wA.z; a3 += hp * wA.w;
            a4 += hp * wB.x; a5 += hp * wB.y; a6 += hp * wB.z; a7 += hp * wB.w;
        }

        // ---- pair reduction: butterfly within the (even,odd) lane pair ----
        a0 += __shfl_xor_sync(0xFFFFFFFFu, a0, 1);
        a1 += __shfl_xor_sync(0xFFFFFFFFu, a1, 1);
        a2 += __shfl_xor_sync(0xFFFFFFFFu, a2, 1);
        a3 += __shfl_xor_sync(0xFFFFFFFFu, a3, 1);
        a4 += __shfl_xor_sync(0xFFFFFFFFu, a4, 1);
        a5 += __shfl_xor_sync(0xFFFFFFFFu, a5, 1);
        a6 += __shfl_xor_sync(0xFFFFFFFFu, a6, 1);
        a7 += __shfl_xor_sync(0xFFFFFFFFu, a7, 1);

        // ---- layer 3 (both lanes, bit-identical) ----
        float y0 = rb3 + fmaxf(a0, 0.0f) * rw3[0];
        float y1 = fmaxf(a1, 0.0f) * rw3[1];
        float y2 = fmaxf(a2, 0.0f) * rw3[2];
        float y3 = fmaxf(a3, 0.0f) * rw3[3];
        y0 += fmaxf(a4, 0.0f) * rw3[4];
        y1 += fmaxf(a5, 0.0f) * rw3[5];
        y2 += fmaxf(a6, 0.0f) * rw3[6];
        y3 += fmaxf(a7, 0.0f) * rw3[7];
        const float y = (y0 + y1) + (y2 + y3);

        // sigmoid * kc * pet (MUFU EX2 + MUFU RCP)
        const float ex = ex2f(-1.442695040888963f * y);
        const float e  = __fdividef(kpet, 1.0f + ex);

        // ---- XAJ water balance (both lanes, bit-identical -> same w) ----
        const float pd     = prcp - e;
        const float pe_net = fmaxf(pd, 0.0f);
        const float resid  = fminf(fmaxf(fmaf(-(pe_net + a_xaj), inv_wmm, 1.0f), 0.0f), 1.0f);
        // resid==0 exactly when pe_net + a >= wmm; ex2(one_b*lg2(0)) = 0,
        // so this is branchlessly identical to the reference's where().
        const float rp  = ex2f(one_b * lg2f(resid));
        const float r   = fmaxf(pe_net + r_base + wm * rp, 0.0f);
        const float rim = pe_net * im;

        w = fminf(fmaxf(w0c + pd - r, 0.0f), wm_eps);

        // even lane: (r, rim); odd lane: (e, pe_net) — adjacent STG.64 coalesce.
        out_ptr[0] = half ? make_float2(e, pe_net) : make_float2(r, rim);
        out_ptr += (size_t)2 * NBASIN;
    }
}

extern "C" void kernel_launch(void* const* d_in, const int* in_sizes, int n_in,
                              void* d_out, int out_size)
{
    (void)in_sizes; (void)n_in; (void)out_size;
    const float2* p_and_e = (const float2*)d_in[0];
    const float*  kc = (const float*)d_in[1];
    const float*  um = (const float*)d_in[2];
    const float*  lm = (const float*)d_in[3];
    const float*  dm = (const float*)d_in[4];
    const float*  b  = (const float*)d_in[5];
    const float*  im = (const float*)d_in[6];
    const float*  c  = (const float*)d_in[7];
    const float*  w0 = (const float*)d_in[8];
    const float*  W1 = (const float*)d_in[9];
    const float*  b1 = (const float*)d_in[10];
    const float*  W2 = (const float*)d_in[11];
    const float*  b2 = (const float*)d_in[12];
    const float*  W3 = (const float*)d_in[13];
    const float*  b3 = (const float*)d_in[14];
    float2* out2 = (float2*)d_out;

    // 32768 threads (2 per basin) = 1024 warps ~= 2 warps/SMSP chip-wide.
    // 512 blocks x 64 threads spread ~3.5 blocks per SM across all 148 SMs.
    xaj_pair_kernel<<<512, 64>>>(p_and_e, kc, um, lm, dm, b, im, c, w0,
                                 W1, b1, W2, b2, W3, b3, out2);
}